// round 13
// baseline (speedup 1.0000x reference)
#include <cuda_runtime.h>
#include <cstdint>

#define BB 16
#define NND 512
#define EE 4
#define HH 64
#define EN 2048
#define A2 4096
#define AD 32
#define STEPS 5
#define GRIDN 128

// ------------- device scratch (no allocations) -------------
__device__ float g_hs  [BB*NND*HH];
__device__ float g_inc [BB*EN*HH];
__device__ float g_outg[BB*EN*HH];
__device__ float g_ain [BB*NND*HH];
__device__ float g_aout[BB*NND*HH];
__device__ float g_att [(size_t)BB*NND*128];
__device__ unsigned g_cnt = 0;
__device__ unsigned g_gen = 0;

// ------------- helpers -------------
__device__ __forceinline__ uint32_t tf(float x){
    uint32_t u; asm("cvt.rna.tf32.f32 %0, %1;" : "=r"(u) : "f"(x));
    return u;
}
__device__ __forceinline__ void tfsplit(float x, uint32_t& hi, uint32_t& lo){
    uint32_t h = tf(x);
    hi = h;
    lo = tf(x - __uint_as_float(h));
}
__device__ __forceinline__ void mma8(float* c, const uint32_t* a, const uint32_t* b){
    asm volatile("mma.sync.aligned.m16n8k8.row.col.f32.tf32.tf32.f32 "
        "{%0,%1,%2,%3}, {%4,%5,%6,%7}, {%8,%9}, {%0,%1,%2,%3};\n"
        : "+f"(c[0]), "+f"(c[1]), "+f"(c[2]), "+f"(c[3])
        : "r"(a[0]), "r"(a[1]), "r"(a[2]), "r"(a[3]), "r"(b[0]), "r"(b[1]));
}
__device__ __forceinline__ float sgm(float x){ return 1.0f/(1.0f + expf(-x)); }
__device__ __forceinline__ uint32_t smem_u32(const void* p){
    uint32_t a;
    asm("{ .reg .u64 t; cvta.to.shared.u64 t, %1; cvt.u32.u64 %0, t; }" : "=r"(a) : "l"(p));
    return a;
}

// grid-wide barrier: all threads fence, block-sync, thread 0 arrives/spins.
__device__ __forceinline__ void grid_sync(){
    __threadfence();
    __syncthreads();
    if (threadIdx.x == 0){
        unsigned gen = atomicAdd(&g_gen, 0u);
        if (atomicAdd(&g_cnt, 1u) == GRIDN - 1u){
            atomicExch(&g_cnt, 0u);
            __threadfence();
            atomicExch(&g_gen, gen + 1u);
        } else {
            while (atomicAdd(&g_gen, 0u) == gen) { }
        }
    }
    __syncthreads();
}

// ---- tf32x3 mma with in-register split; raw fp32 smem operands ----
template<int LDA, int LDB, int KS, int NI>
__device__ __forceinline__ void mma_frag(
    const float* sA, const float* sB,
    int mrow, int ncol, int gid, int q,
    float accM[2][NI][4], float accC[2][NI][4])
{
    #pragma unroll
    for (int ks = 0; ks < KS; ks++){
        const int k0 = ks*8;
        uint32_t ah[2][4], al[2][4];
        #pragma unroll
        for (int mi = 0; mi < 2; mi++){
            const int r = mrow + mi*16 + gid;
            tfsplit(sA[r*LDA+k0+q],       ah[mi][0], al[mi][0]);
            tfsplit(sA[(r+8)*LDA+k0+q],   ah[mi][1], al[mi][1]);
            tfsplit(sA[r*LDA+k0+q+4],     ah[mi][2], al[mi][2]);
            tfsplit(sA[(r+8)*LDA+k0+q+4], ah[mi][3], al[mi][3]);
        }
        #pragma unroll
        for (int ni = 0; ni < NI; ni++){
            const int c = ncol + ni*8 + gid;
            uint32_t bh[2], bl[2];
            tfsplit(sB[(k0+q)*LDB+c],   bh[0], bl[0]);
            tfsplit(sB[(k0+q+4)*LDB+c], bh[1], bl[1]);
            #pragma unroll
            for (int mi = 0; mi < 2; mi++){
                mma8(accM[mi][ni], ah[mi], bh);
                mma8(accC[mi][ni], al[mi], bh);
                mma8(accC[mi][ni], ah[mi], bl);
            }
        }
    }
}

// =====================================================================
// phase: proj — 2 tiles per CTA (256 tiles total). smem: A[128][68] +
// Wi[64][72] + Wo[64][72] = 71.7KB. Warp tile 32x32 (4m x 2n).
// =====================================================================
__device__ void proj_phase(const float* __restrict__ inw, const float* __restrict__ inb,
                           const float* __restrict__ outw, const float* __restrict__ outb,
                           float* sm){
    float* sA  = sm;             // 128*68
    float* sW1 = sA + 128*68;    // 64*72
    float* sW2 = sW1 + 64*72;    // 64*72
    const int t = threadIdx.x;
    const int warp = t>>5, lane = t&31, gid = lane>>2, q = lane&3;
    const int mrow = (warp>>1)*32, ncol = (warp&1)*32;

    for (int tile = blockIdx.x; tile < 256; tile += GRIDN){
        const int mt = tile & 3, e = (tile>>2)&3, b = tile>>4;
        __syncthreads();                         // prior smem readers done
        const float* hsP = g_hs + ((size_t)b*NND + mt*128)*HH;
        #pragma unroll
        for (int j = 0; j < 8; j++){
            int idx = t + j*256, r = idx>>4, c = (idx&15)*4;
            *reinterpret_cast<float4*>(sA + r*68 + c) =
                *reinterpret_cast<const float4*>(hsP + (size_t)r*HH + c);
        }
        const float* wi = inw + (size_t)e*4096;
        const float* wo = outw + (size_t)e*4096;
        #pragma unroll
        for (int j = 0; j < 4; j++){
            int idx = t + j*256, r = idx>>4, c = (idx&15)*4;
            *reinterpret_cast<float4*>(sW1 + r*72 + c) = *reinterpret_cast<const float4*>(wi + (size_t)r*64 + c);
            *reinterpret_cast<float4*>(sW2 + r*72 + c) = *reinterpret_cast<const float4*>(wo + (size_t)r*64 + c);
        }
        __syncthreads();

        const size_t mBase = (size_t)b*EN + (size_t)e*NND + (size_t)mt*128;
        {
            float aM[2][4][4] = {}, aC[2][4][4] = {};
            mma_frag<68,72,8,4>(sA, sW1, mrow, ncol, gid, q, aM, aC);
            #pragma unroll
            for (int mi = 0; mi < 2; mi++)
            #pragma unroll
            for (int ni = 0; ni < 4; ni++)
            #pragma unroll
            for (int e2 = 0; e2 < 4; e2++){
                const int fr = mrow + mi*16 + gid + ((e2&2)?8:0);
                const int fc = ncol + ni*8 + q*2 + (e2&1);
                g_inc[(mBase+fr)*HH + fc] = (aM[mi][ni][e2] + aC[mi][ni][e2]) + __ldg(inb + e*64 + fc);
            }
        }
        {
            float aM[2][4][4] = {}, aC[2][4][4] = {};
            mma_frag<68,72,8,4>(sA, sW2, mrow, ncol, gid, q, aM, aC);
            #pragma unroll
            for (int mi = 0; mi < 2; mi++)
            #pragma unroll
            for (int ni = 0; ni < 4; ni++)
            #pragma unroll
            for (int e2 = 0; e2 < 4; e2++){
                const int fr = mrow + mi*16 + gid + ((e2&2)?8:0);
                const int fc = ncol + ni*8 + q*2 + (e2&1);
                g_outg[(mBase+fr)*HH + fc] = (aM[mi][ni][e2] + aC[mi][ni][e2]) + __ldg(outb + e*64 + fc);
            }
        }
    }
}

// =====================================================================
// phase: bmm — 1 tile per CTA. cp.async 4-stage, raw fp32 smem,
// split-in-register tf32x3, fp64 drain every 16 chunks.
// Stage = A[128][36] + B[32][72] = 6912 floats; 4 stages = 110592 B.
// =====================================================================
#define BMM_STG 6912
__device__ __forceinline__ void bmm_issue_chunk(
    const float* Ag, const float* Bg, uint32_t sA_u32, uint32_t sB_u32,
    int kk, int t)
{
    #pragma unroll
    for (int j = 0; j < 4; j++){                 // A: 1024 x 16B granules
        int g = t + j*256, r = g>>3, c4 = (g&7)*4;
        uint32_t dst = sA_u32 + (uint32_t)(r*36 + c4)*4;
        const float* src = Ag + (size_t)r*A2 + kk + c4;
        asm volatile("cp.async.cg.shared.global [%0], [%1], 16;" :: "r"(dst), "l"(src));
    }
    #pragma unroll
    for (int j = 0; j < 2; j++){                 // B: 512 x 16B granules
        int g = t + j*256, r = g>>4, c4 = (g&15)*4;
        uint32_t dst = sB_u32 + (uint32_t)(r*72 + c4)*4;
        const float* src = Bg + (size_t)(kk + r)*HH + c4;
        asm volatile("cp.async.cg.shared.global [%0], [%1], 16;" :: "r"(dst), "l"(src));
    }
    asm volatile("cp.async.commit_group;" ::: "memory");
}

__device__ void bmm_phase(const float* __restrict__ Abig, float* sm){
    const int x = blockIdx.x;
    const int mt = x & 3, bh = x >> 2, b = bh>>1, half = bh&1;
    const int t = threadIdx.x;
    const float* Ag = Abig + ((size_t)b*NND + mt*128)*A2 + (size_t)half*EN;
    const float* Bg = (half ? g_outg : g_inc) + (size_t)b*EN*HH;
    float*       Cg = (half ? g_aout : g_ain) + ((size_t)b*NND + mt*128)*HH;
    const uint32_t sbase = smem_u32(sm);

    bmm_issue_chunk(Ag, Bg, sbase, sbase + 4608u*4, 0, t);
    bmm_issue_chunk(Ag, Bg, sbase + (uint32_t)BMM_STG*4, sbase + (uint32_t)(BMM_STG+4608)*4, 32, t);

    const int warp = t>>5, lane = t&31, gid = lane>>2, q = lane&3;
    const int mrow = (warp>>1)*32, ncol = (warp&1)*32;
    float accM[2][4][4] = {}, accC[2][4][4] = {};
    double accD[2][4][4] = {};

    for (int it = 0; it < 64; it++){
        if (it + 2 < 64){
            const uint32_t sb = sbase + (uint32_t)(((it+2)&3)*BMM_STG)*4;
            bmm_issue_chunk(Ag, Bg, sb, sb + 4608u*4, (it+2)*32, t);
        }
        if (it < 62)       asm volatile("cp.async.wait_group 2;" ::: "memory");
        else if (it == 62) asm volatile("cp.async.wait_group 1;" ::: "memory");
        else               asm volatile("cp.async.wait_group 0;" ::: "memory");
        __syncthreads();
        const float* base = sm + (it&3)*BMM_STG;
        mma_frag<36,72,4,4>(base, base + 4608, mrow, ncol, gid, q, accM, accC);
        if ((it & 15) == 15){
            #pragma unroll
            for (int mi = 0; mi < 2; mi++)
            #pragma unroll
            for (int ni = 0; ni < 4; ni++)
            #pragma unroll
            for (int e2 = 0; e2 < 4; e2++){
                accD[mi][ni][e2] += (double)accM[mi][ni][e2] + (double)accC[mi][ni][e2];
                accM[mi][ni][e2] = 0.0f;
                accC[mi][ni][e2] = 0.0f;
            }
        }
        __syncthreads();
    }
    #pragma unroll
    for (int mi = 0; mi < 2; mi++)
    #pragma unroll
    for (int ni = 0; ni < 4; ni++)
    #pragma unroll
    for (int e2 = 0; e2 < 4; e2++){
        const int fr = mrow + mi*16 + gid + ((e2&2)?8:0);
        const int fc = ncol + ni*8 + q*2 + (e2&1);
        Cg[(size_t)fr*HH + fc] = (float)accD[mi][ni][e2];
    }
}

// =====================================================================
// phase: gate — fused GRU gates, 1 x 64-node tile per CTA.
// smem: sA[64][196], sG[64][196], sW[32][72] = 109.6KB
// =====================================================================
__device__ void gate_phase(const float* __restrict__ uw, const float* __restrict__ rw,
                           const float* __restrict__ tw, const float* __restrict__ ub,
                           const float* __restrict__ rb, const float* __restrict__ tb,
                           float* sm){
    float* sA = sm;                  // 64*196
    float* sG = sA + 64*196;         // 64*196
    float* sW = sG + 64*196;         // 32*72
    const int mt = blockIdx.x & 7, b = blockIdx.x >> 3, t = threadIdx.x;
    const size_t nodeBase = (size_t)b*NND + (size_t)mt*64;

    {
        const float* srcs[3] = { g_ain + nodeBase*HH, g_aout + nodeBase*HH, g_hs + nodeBase*HH };
        #pragma unroll
        for (int s = 0; s < 3; s++){
            #pragma unroll
            for (int j = 0; j < 4; j++){
                int idx = t + j*256, r = idx>>4, c = (idx&15)*4;
                *reinterpret_cast<float4*>(sA + r*196 + s*64 + c) =
                    *reinterpret_cast<const float4*>(srcs[s] + (size_t)r*HH + c);
            }
        }
    }
    __syncthreads();

    const int warp = t>>5, lane = t&31, gid = lane>>2, q = lane&3;
    const int mrow = (warp>>2)*32, ncol = (warp&3)*16;

    #pragma unroll
    for (int nt = 0; nt < 3; nt++){
        const float* W    = (nt==0) ? uw : (nt==1) ? rw : tw;
        const float* bias = (nt==0) ? ub : (nt==1) ? rb : tb;
        const int kmax = (nt==2) ? 4 : 6;
        float accM[2][2][4] = {}, accC[2][2][4] = {};
        for (int kc = 0; kc < kmax; kc++){
            #pragma unroll
            for (int j = 0; j < 2; j++){
                int idx = t + j*256, r = idx>>4, c = (idx&15)*4;
                *reinterpret_cast<float4*>(sW + r*72 + c) =
                    *reinterpret_cast<const float4*>(W + (size_t)(kc*32+r)*64 + c);
            }
            __syncthreads();
            mma_frag<196,72,4,2>(sA + kc*32, sW, mrow, ncol, gid, q, accM, accC);
            __syncthreads();
        }
        #pragma unroll
        for (int mi = 0; mi < 2; mi++)
        #pragma unroll
        for (int ni = 0; ni < 2; ni++)
        #pragma unroll
        for (int e2 = 0; e2 < 4; e2++){
            const int fr = mrow + mi*16 + gid + ((e2&2)?8:0);
            const int fc = ncol + ni*8 + q*2 + (e2&1);
            sG[fr*196 + nt*64 + fc] = (accM[mi][ni][e2] + accC[mi][ni][e2]) + __ldg(bias + fc);
        }
    }
    __syncthreads();

    #pragma unroll
    for (int j = 0; j < 16; j++){
        int idx = t + j*256, r = idx>>6, c = idx&63;
        sA[r*196 + c] = sA[r*196 + 128 + c] * sgm(sG[r*196 + 64 + c]);
    }
    __syncthreads();

    float acc2M[2][2][4] = {}, acc2C[2][2][4] = {};
    for (int kc = 0; kc < 2; kc++){
        #pragma unroll
        for (int j = 0; j < 2; j++){
            int idx = t + j*256, r = idx>>4, c = (idx&15)*4;
            *reinterpret_cast<float4*>(sW + r*72 + c) =
                *reinterpret_cast<const float4*>(tw + (size_t)(128 + kc*32 + r)*64 + c);
        }
        __syncthreads();
        mma_frag<196,72,4,2>(sA + kc*32, sW, mrow, ncol, gid, q, acc2M, acc2C);
        __syncthreads();
    }

    #pragma unroll
    for (int mi = 0; mi < 2; mi++)
    #pragma unroll
    for (int ni = 0; ni < 2; ni++)
    #pragma unroll
    for (int e2 = 0; e2 < 4; e2++){
        const int fr = mrow + mi*16 + gid + ((e2&2)?8:0);
        const int fc = ncol + ni*8 + q*2 + (e2&1);
        const size_t node = nodeBase + fr;
        float z  = sgm(sG[fr*196 + fc]);
        float h  = tanhf(sG[fr*196 + 128 + fc] + (acc2M[mi][ni][e2] + acc2C[mi][ni][e2]));
        float hv = sA[fr*196 + 128 + fc];
        g_hs[node*HH + fc] = (1.0f - z)*hv + z*h;
    }
}

// =====================================================================
// phase: att — 1 tile per CTA (mt 0-3, b 0-15, nt 0-1)
// =====================================================================
__device__ void att_phase(const float* __restrict__ ann, const float* __restrict__ aw,
                          const float* __restrict__ ab, const float* __restrict__ sw,
                          const float* __restrict__ sb, float* sm){
    float* sA = sm;           // 128*36
    float* sB = sA + 128*36;  // 32*72
    const int x = blockIdx.x;
    const int mt = x & 3, b = (x>>2)&15, nt = x>>6;
    const int t = threadIdx.x;
    const float* W    = nt ? sw : aw;
    const float* bias = nt ? sb : ab;
    const size_t nodeBase = (size_t)b*NND + (size_t)mt*128;
    const int warp = t>>5, lane = t&31, gid = lane>>2, q = lane&3;
    const int mrow = (warp>>1)*32, ncol = (warp&1)*32;
    float accM[2][4][4] = {}, accC[2][4][4] = {};
    for (int kc = 0; kc < 3; kc++){
        const int k0 = kc*32;
        const float* Ag; int rs;
        if (kc < 2){ Ag = g_hs + nodeBase*HH + k0; rs = HH; }
        else       { Ag = ann + nodeBase*AD;       rs = AD; }
        #pragma unroll
        for (int j = 0; j < 4; j++){
            int idx = t + j*256, r = idx>>3, c = (idx&7)*4;
            *reinterpret_cast<float4*>(sA + r*36 + c) =
                *reinterpret_cast<const float4*>(Ag + (size_t)r*rs + c);
        }
        #pragma unroll
        for (int j = 0; j < 2; j++){
            int idx = t + j*256, r = idx>>4, c = (idx&15)*4;
            *reinterpret_cast<float4*>(sB + r*72 + c) =
                *reinterpret_cast<const float4*>(W + (size_t)(k0+r)*64 + c);
        }
        __syncthreads();
        mma_frag<36,72,4,4>(sA, sB, mrow, ncol, gid, q, accM, accC);
        __syncthreads();
    }
    #pragma unroll
    for (int mi = 0; mi < 2; mi++)
    #pragma unroll
    for (int ni = 0; ni < 4; ni++)
    #pragma unroll
    for (int e2 = 0; e2 < 4; e2++){
        const int fr = mrow + mi*16 + gid + ((e2&2)?8:0);
        const int fc = ncol + ni*8 + q*2 + (e2&1);
        g_att[(nodeBase+fr)*128 + nt*64 + fc] =
            (accM[mi][ni][e2] + accC[mi][ni][e2]) + __ldg(bias + fc);
    }
}

// =====================================================================
// phase: reduce — CTAs 0..15, fp64
// =====================================================================
__device__ void reduce_phase(float* __restrict__ out, float* sm){
    if (blockIdx.x >= BB) return;
    double* red = reinterpret_cast<double*>(sm);
    const int b = blockIdx.x, t = threadIdx.x;
    const int c = t & 63, seg = t >> 6;
    double acc = 0.0;
    for (int n = seg; n < NND; n += 4){
        const float* p = g_att + ((size_t)b*NND + n)*128;
        double attn = 1.0/(1.0 + exp(-(double)p[c]));
        double ts   = tanh((double)p[64 + c]);
        acc += attn * ts;
    }
    red[t] = acc;
    __syncthreads();
    if (t < 64){
        double s = red[t] + red[t+64] + red[t+128] + red[t+192];
        out[(size_t)b*64 + t] = (float)tanh(s);
    }
}

// =====================================================================
// the one persistent kernel
// =====================================================================
__global__ void __launch_bounds__(256, 1)
ggnn_fused(const float* __restrict__ ann, const float* __restrict__ Abig,
           const float* __restrict__ inw, const float* __restrict__ inb,
           const float* __restrict__ outw, const float* __restrict__ outb,
           const float* __restrict__ uw, const float* __restrict__ ub,
           const float* __restrict__ rw, const float* __restrict__ rb,
           const float* __restrict__ tw, const float* __restrict__ tb,
           const float* __restrict__ aw, const float* __restrict__ ab,
           const float* __restrict__ sw, const float* __restrict__ sb,
           float* __restrict__ out)
{
    extern __shared__ float sm[];
    for (int s = 0; s < STEPS; s++){
        proj_phase(inw, inb, outw, outb, sm);
        grid_sync();
        bmm_phase(Abig, sm);
        grid_sync();
        gate_phase(uw, rw, tw, ub, rb, tb, sm);
        grid_sync();
    }
    att_phase(ann, aw, ab, sw, sb, sm);
    grid_sync();
    reduce_phase(out, sm);
}

// =====================================================================
extern "C" void kernel_launch(void* const* d_in, const int* in_sizes, int n_in,
                              void* d_out, int out_size){
    const float* hs   = (const float*)d_in[0];
    const float* ann  = (const float*)d_in[1];
    const float* Abig = (const float*)d_in[2];
    const float* inw  = (const float*)d_in[3];
    const float* inb  = (const float*)d_in[4];
    const float* outw = (const float*)d_in[5];
    const float* outb = (const float*)d_in[6];
    const float* uw   = (const float*)d_in[7];
    const float* ub   = (const float*)d_in[8];
    const float* rw   = (const float*)d_in[9];
    const float* rb   = (const float*)d_in[10];
    const float* tw   = (const float*)d_in[11];
    const float* tb   = (const float*)d_in[12];
    const float* aw   = (const float*)d_in[13];
    const float* ab   = (const float*)d_in[14];
    const float* sw   = (const float*)d_in[15];
    const float* sb   = (const float*)d_in[16];

    const int SMEM = 4 * BMM_STG * 4;            // 110592 B (max of all phases)
    cudaFuncSetAttribute(ggnn_fused, cudaFuncAttributeMaxDynamicSharedMemorySize, SMEM);

    cudaMemcpyToSymbolAsync(g_hs, hs, sizeof(float)*BB*NND*HH, 0,
                            cudaMemcpyDeviceToDevice, 0);

    ggnn_fused<<<GRIDN, 256, SMEM>>>(ann, Abig, inw, inb, outw, outb,
                                     uw, ub, rw, rb, tw, tb,
                                     aw, ab, sw, sb, (float*)d_out);
}